// round 12
// baseline (speedup 1.0000x reference)
#include <cuda_runtime.h>
#include <cstddef>

// SegmentedPolynomialProductJit: out[e,k,u] = sum_{paths (i,j,k,c)} c * a[idx_a[e], i, u] * b[e, j, u]
// scatter-added into out[idx_out[e]].
// SA=4, SB=3, SC=4, U=32, paths: all (i,j), k=(i+j)%4, c=0.1*(i+1)+0.01*(j+1).
//
// R4: DRAM-bound, 1.0 GB HBM vs ~590 MB floor (b stream thrashing L2).
// R8: __ldcs on b -> 775 MB, 129 us kernel. Confirmed theory, partial recovery.
// R9-R11: pin a explicitly. sm_103a allows .L2::evict_* only on v8.b32/v4.b64 loads,
// so move to 4 threads/edge, 32 B per segment per thread:
//   a: ld.global.nc.L2::evict_last.v8.b32 (pin 51 MB gather set)
//   b: ld.global.nc.L2::evict_first.v8.b32 (384 MB read-once stream)

#define SA 4
#define SB 3
#define SC 4
#define UE 32
#define A_ROW (SA * UE)   // 128 floats
#define B_ROW (SB * UE)   // 96 floats
#define O_ROW (SC * UE)   // 128 floats

__device__ __forceinline__ void ld8_last(const float* p, float* r) {
    asm("ld.global.nc.L2::evict_last.v8.b32 {%0,%1,%2,%3,%4,%5,%6,%7}, [%8];"
        : "=f"(r[0]), "=f"(r[1]), "=f"(r[2]), "=f"(r[3]),
          "=f"(r[4]), "=f"(r[5]), "=f"(r[6]), "=f"(r[7])
        : "l"(p));
}

__device__ __forceinline__ void ld8_first(const float* p, float* r) {
    asm("ld.global.nc.L2::evict_first.v8.b32 {%0,%1,%2,%3,%4,%5,%6,%7}, [%8];"
        : "=f"(r[0]), "=f"(r[1]), "=f"(r[2]), "=f"(r[3]),
          "=f"(r[4]), "=f"(r[5]), "=f"(r[6]), "=f"(r[7])
        : "l"(p));
}

// 4 threads per edge; each thread owns 8 consecutive u (32 B) across all segments.
__global__ __launch_bounds__(256) void spp_kernel(
    const float* __restrict__ a,
    const float* __restrict__ b,
    const int*   __restrict__ idx_a,
    const int*   __restrict__ idx_out,
    float*       __restrict__ out,
    int E)
{
    long long tid = (long long)blockIdx.x * blockDim.x + threadIdx.x;
    int e = (int)(tid >> 2);
    if (e >= E) return;
    int q = (int)(tid & 3);          // 8-float chunk index within a U=32 segment

    const int ia = __ldg(idx_a + e);
    const int io = __ldg(idx_out + e);

    const float* arow = a + (size_t)ia * A_ROW + q * 8;
    const float* brow = b + (size_t)e  * B_ROW + q * 8;

    float A[SA][8], B[SB][8];
#pragma unroll
    for (int i = 0; i < SA; i++) ld8_last(arow + i * UE, A[i]);
#pragma unroll
    for (int j = 0; j < SB; j++) ld8_first(brow + j * UE, B[j]);

    float O[SC][8];
#pragma unroll
    for (int k = 0; k < SC; k++)
#pragma unroll
        for (int u = 0; u < 8; u++) O[k][u] = 0.f;

#pragma unroll
    for (int i = 0; i < SA; i++) {
#pragma unroll
        for (int j = 0; j < SB; j++) {
            const int k = (i + j) & 3;
            const float c = 0.1f * (float)(i + 1) + 0.01f * (float)(j + 1);
#pragma unroll
            for (int u = 0; u < 8; u++)
                O[k][u] = fmaf(c * A[i][u], B[j][u], O[k][u]);
        }
    }

    float* orow = out + (size_t)io * O_ROW + q * 8;
#pragma unroll
    for (int k = 0; k < SC; k++) {
        float* p = orow + k * UE;
        asm volatile("red.global.add.v4.f32 [%0], {%1, %2, %3, %4};"
                     :: "l"(p), "f"(O[k][0]), "f"(O[k][1]), "f"(O[k][2]), "f"(O[k][3])
                     : "memory");
        asm volatile("red.global.add.v4.f32 [%0], {%1, %2, %3, %4};"
                     :: "l"(p + 4), "f"(O[k][4]), "f"(O[k][5]), "f"(O[k][6]), "f"(O[k][7])
                     : "memory");
    }
}

extern "C" void kernel_launch(void* const* d_in, const int* in_sizes, int n_in,
                              void* d_out, int out_size)
{
    const float* a       = (const float*)d_in[0];
    const float* b       = (const float*)d_in[1];
    const int*   idx_a   = (const int*)d_in[2];
    const int*   idx_out = (const int*)d_in[3];
    float*       out     = (float*)d_out;

    const int E = in_sizes[1] / B_ROW;

    // Output buffer is poisoned by the harness; zero it (memset node is graph-capturable).
    cudaMemsetAsync(d_out, 0, (size_t)out_size * sizeof(float));

    const int threads = 256;
    const long long total = (long long)E * 4;
    const int blocks = (int)((total + threads - 1) / threads);
    spp_kernel<<<blocks, threads>>>(a, b, idx_a, idx_out, out, E);
}

// round 13
// speedup vs baseline: 1.3747x; 1.3747x over previous
#include <cuda_runtime.h>
#include <cstddef>

// SegmentedPolynomialProductJit: out[e,k,u] = sum_{paths (i,j,k,c)} c * a[idx_a[e], i, u] * b[e, j, u]
// scatter-added into out[idx_out[e]].
// SA=4, SB=3, SC=4, U=32, paths: all (i,j), k=(i+j)%4, c=0.1*(i+1)+0.01*(j+1).
//
// Evidence log:
// R4:  baseline 150.9us, 1.0 GB HBM (83.6% SOL) vs ~590 MB floor -> b-stream L2 thrash.
// R8:  __ldcs on b -> 129.0us, 775 MB. WIN, theory confirmed.
// R12: 4thr/edge + v8 evict_last/evict_first -> 175us, traffic UNCHANGED (783 MB),
//      occ 30.8%. Lessons: evict_last pinning ineffective; occupancy is critical.
// R13: revert to R8 structure; single delta = 128-thread blocks for finer
//      register-file packing (46 regs: 11x128=1408 thr/SM vs 5x256=1280).

#define SA 4
#define SB 3
#define SC 4
#define UE 32
#define A_ROW (SA * UE)   // 128 floats
#define B_ROW (SB * UE)   // 96 floats
#define O_ROW (SC * UE)   // 128 floats

// 8 threads per edge; each thread owns one float4 (4 consecutive u) across all segments.
__global__ __launch_bounds__(128) void spp_kernel(
    const float* __restrict__ a,
    const float* __restrict__ b,
    const int*   __restrict__ idx_a,
    const int*   __restrict__ idx_out,
    float*       __restrict__ out,
    int E)
{
    long long tid = (long long)blockIdx.x * blockDim.x + threadIdx.x;
    int e = (int)(tid >> 3);
    if (e >= E) return;
    int q = (int)(tid & 7);          // float4 index within a U=32 segment (8 quads)

    const int ia = __ldg(idx_a + e);
    const int io = __ldg(idx_out + e);

    const float4* arow = reinterpret_cast<const float4*>(a) + (size_t)ia * (A_ROW / 4) + q;
    const float4* brow = reinterpret_cast<const float4*>(b) + (size_t)e  * (B_ROW / 4) + q;

    float4 A[SA], B[SB];
#pragma unroll
    for (int i = 0; i < SA; i++) A[i] = __ldg(arow + i * (UE / 4));      // reused: keep cached
#pragma unroll
    for (int j = 0; j < SB; j++) B[j] = __ldcs(brow + j * (UE / 4));     // read-once: streaming

    float4 O[SC];
#pragma unroll
    for (int k = 0; k < SC; k++) { O[k].x = 0.f; O[k].y = 0.f; O[k].z = 0.f; O[k].w = 0.f; }

#pragma unroll
    for (int i = 0; i < SA; i++) {
#pragma unroll
        for (int j = 0; j < SB; j++) {
            const int k = (i + j) & 3;
            const float c = 0.1f * (float)(i + 1) + 0.01f * (float)(j + 1);
            // pre-scale a by the path coefficient, then one fma per component
            float cax = c * A[i].x;
            float cay = c * A[i].y;
            float caz = c * A[i].z;
            float caw = c * A[i].w;
            O[k].x = fmaf(cax, B[j].x, O[k].x);
            O[k].y = fmaf(cay, B[j].y, O[k].y);
            O[k].z = fmaf(caz, B[j].z, O[k].z);
            O[k].w = fmaf(caw, B[j].w, O[k].w);
        }
    }

    float* orow = out + (size_t)io * O_ROW + q * 4;
#pragma unroll
    for (int k = 0; k < SC; k++) {
        float* p = orow + k * UE;
        asm volatile("red.global.add.v4.f32 [%0], {%1, %2, %3, %4};"
                     :: "l"(p), "f"(O[k].x), "f"(O[k].y), "f"(O[k].z), "f"(O[k].w)
                     : "memory");
    }
}

extern "C" void kernel_launch(void* const* d_in, const int* in_sizes, int n_in,
                              void* d_out, int out_size)
{
    const float* a       = (const float*)d_in[0];
    const float* b       = (const float*)d_in[1];
    const int*   idx_a   = (const int*)d_in[2];
    const int*   idx_out = (const int*)d_in[3];
    float*       out     = (float*)d_out;

    const int E = in_sizes[1] / B_ROW;

    // Output buffer is poisoned by the harness; zero it (memset node is graph-capturable).
    cudaMemsetAsync(d_out, 0, (size_t)out_size * sizeof(float));

    const int threads = 128;
    const long long total = (long long)E * 8;
    const int blocks = (int)((total + threads - 1) / threads);
    spp_kernel<<<blocks, threads>>>(a, b, idx_a, idx_out, out, E);
}